// round 1
// baseline (speedup 1.0000x reference)
#include <cuda_runtime.h>

#define D   512
#define NW  64
#define MT  128
#define KT  32
#define NKT (D / KT)
#define NTHREADS 256

// Proto norms (computed once per launch by a tiny kernel; no allocations).
__device__ float g_pn[NW];
__device__ float g_ipn[NW];

__global__ void proto_norm_kernel(const float* __restrict__ p) {
    int c = blockIdx.x;     // one block per prototype
    int t = threadIdx.x;    // 128 threads
    float s = 0.f;
    #pragma unroll
    for (int k = t; k < D; k += 128) { float v = p[c * D + k]; s += v * v; }
    #pragma unroll
    for (int o = 16; o; o >>= 1) s += __shfl_xor_sync(0xffffffffu, s, o);
    __shared__ float ws[4];
    if ((t & 31) == 0) ws[t >> 5] = s;
    __syncthreads();
    if (t == 0) {
        float n2 = ws[0] + ws[1] + ws[2] + ws[3];
        float pn = sqrtf(n2);
        g_pn[c]  = pn;
        g_ipn[c] = 1.0f / pn;
    }
}

__device__ __forceinline__ unsigned long long pack2(float x, float y) {
    unsigned long long r;
    asm("mov.b64 %0, {%1, %2};" : "=l"(r) : "f"(x), "f"(y));
    return r;
}
__device__ __forceinline__ void unpack2(unsigned long long v, float& x, float& y) {
    asm("mov.b64 {%0, %1}, %2;" : "=f"(x), "=f"(y) : "l"(v));
}
// Packed dual-FMA: (d.lo,d.hi) += (a.lo*b.lo, a.hi*b.hi). PTX-only on sm_103a.
__device__ __forceinline__ void fma2(unsigned long long& d, unsigned long long a,
                                     unsigned long long b) {
    asm("fma.rn.f32x2 %0, %1, %2, %0;" : "+l"(d) : "l"(a), "l"(b));
}

__global__ __launch_bounds__(NTHREADS) void cosine_kernel(
    const float* __restrict__ x, const float* __restrict__ protos,
    float* __restrict__ out) {

    __shared__ float As[MT][KT + 4];   // [row][k], pad keeps float4 stores aligned
    __shared__ float Bs[KT][NW + 2];   // [k][proto], pairs 8B-aligned for f32x2
    __shared__ float xn2s[MT];
    __shared__ float spn[NW], sipn[NW];

    const int t    = threadIdx.x;
    const int tx   = t & 7;        // proto octet: protos 8*tx .. 8*tx+7
    const int ty   = t >> 3;       // row quad:   rows  4*ty .. 4*ty+3
    const int lrow = t >> 3;       // loader row-in-group (0..31)
    const int lk4  = (t & 7) * 4;  // loader k offset within tile

    const long rowBase = (long)blockIdx.x * MT;
    const float* xg = x + rowBase * D;

    if (t < NW) { spn[t] = g_pn[t]; sipn[t] = g_ipn[t]; }

    unsigned long long acc[4][4];   // [row][proto-pair]
    #pragma unroll
    for (int i = 0; i < 4; i++)
        #pragma unroll
        for (int j = 0; j < 4; j++) acc[i][j] = 0ull;

    float na[4] = {0.f, 0.f, 0.f, 0.f};   // partial ||x||^2 for loaded rows

    float4 va[4], vb[2];
    // prologue global loads (tile 0)
    #pragma unroll
    for (int p = 0; p < 4; p++)
        va[p] = *(const float4*)&xg[(p * 32 + lrow) * D + lk4];
    #pragma unroll
    for (int q = 0; q < 2; q++)
        vb[q] = *(const float4*)&protos[(q * 32 + lrow) * D + lk4];

    for (int kt = 0; kt < NKT; ++kt) {
        // ---- stage current tile into smem + fuse row-norm accumulation ----
        #pragma unroll
        for (int p = 0; p < 4; p++) {
            int r = p * 32 + lrow;
            *(float4*)&As[r][lk4] = va[p];
            na[p] += va[p].x * va[p].x + va[p].y * va[p].y
                   + va[p].z * va[p].z + va[p].w * va[p].w;
        }
        #pragma unroll
        for (int q = 0; q < 2; q++) {
            int c = q * 32 + lrow;
            Bs[lk4 + 0][c] = vb[q].x;
            Bs[lk4 + 1][c] = vb[q].y;
            Bs[lk4 + 2][c] = vb[q].z;
            Bs[lk4 + 3][c] = vb[q].w;
        }
        __syncthreads();

        // ---- prefetch next tile (overlaps with compute below) ----
        if (kt + 1 < NKT) {
            int k0 = (kt + 1) * KT;
            #pragma unroll
            for (int p = 0; p < 4; p++)
                va[p] = *(const float4*)&xg[(p * 32 + lrow) * D + k0 + lk4];
            #pragma unroll
            for (int q = 0; q < 2; q++)
                vb[q] = *(const float4*)&protos[(q * 32 + lrow) * D + k0 + lk4];
        }

        // ---- FMA2 mainloop: 16 fma.rn.f32x2 per k-step = 32 fp32 FMAs ----
        #pragma unroll
        for (int kk = 0; kk < KT; ++kk) {
            unsigned long long a2[4];
            #pragma unroll
            for (int i = 0; i < 4; i++) {
                float av = As[4 * ty + i][kk];
                a2[i] = pack2(av, av);
            }
            #pragma unroll
            for (int j = 0; j < 4; j++) {
                float2 bv = *(const float2*)&Bs[kk][8 * tx + 2 * j];
                unsigned long long b2 = pack2(bv.x, bv.y);
                #pragma unroll
                for (int i = 0; i < 4; i++) fma2(acc[i][j], a2[i], b2);
            }
        }
        __syncthreads();
    }

    // ---- reduce row norms across the 8 threads that loaded each row ----
    #pragma unroll
    for (int p = 0; p < 4; p++) {
        #pragma unroll
        for (int o = 1; o < 8; o <<= 1)
            na[p] += __shfl_xor_sync(0xffffffffu, na[p], o);
    }
    if ((t & 7) == 0) {
        #pragma unroll
        for (int p = 0; p < 4; p++) xn2s[p * 32 + (t >> 3)] = na[p];
    }
    __syncthreads();

    // ---- epilogue: out = -dot / max(|x||p|, 1e-8) ----
    float* og = out + rowBase * NW;
    #pragma unroll
    for (int i = 0; i < 4; i++) {
        int r = 4 * ty + i;
        float n2    = xn2s[r];
        float invxn = rsqrtf(n2);
        float xn    = n2 * invxn;     // = sqrt(n2)
        float res[8];
        #pragma unroll
        for (int j = 0; j < 4; j++) {
            float d0, d1;
            unpack2(acc[i][j], d0, d1);
            int c = 8 * tx + 2 * j;
            float r0 = invxn * sipn[c];
            float r1 = invxn * sipn[c + 1];
            if (xn * spn[c]     < 1e-8f) r0 = 1e8f;   // max(denom, eps) branch
            if (xn * spn[c + 1] < 1e-8f) r1 = 1e8f;
            res[2 * j]     = -d0 * r0;
            res[2 * j + 1] = -d1 * r1;
        }
        *(float4*)&og[(long)r * NW + 8 * tx]     = make_float4(res[0], res[1], res[2], res[3]);
        *(float4*)&og[(long)r * NW + 8 * tx + 4] = make_float4(res[4], res[5], res[6], res[7]);
    }
}

extern "C" void kernel_launch(void* const* d_in, const int* in_sizes, int n_in,
                              void* d_out, int out_size) {
    const float* x      = (const float*)d_in[0];
    const float* protos = (const float*)d_in[1];
    float* out          = (float*)d_out;
    int B = in_sizes[0] / D;           // 65536

    proto_norm_kernel<<<NW, 128>>>(protos);
    cosine_kernel<<<B / MT, NTHREADS>>>(x, protos, out);
}

// round 4
// speedup vs baseline: 1.7158x; 1.7158x over previous
#include <cuda_runtime.h>
#include <cstdint>

#define D     512
#define NWAY  64
#define MT    128
#define KT    64
#define NCH   (D / KT)     // 8
#define NTH   256

// ---- dynamic smem layout (tile bases 1024-aligned) ----
#define A_MAT  16384                    // 128x64 bf16
#define A_BUF  (2 * A_MAT)              // hi + lo
#define B_MAT  65536                    // 512x64 bf16 ([k][n])
#define SM_XN2  0                       // 128 floats
#define SM_SPN  512                     // 64 floats
#define SM_SIPN 768                     // 64 floats
#define SM_A    1024                    // 2 buffers x (hi,lo) = 64KB
#define SM_B    (SM_A + 2 * A_BUF)      // 66560: BHI 64KB, BLO 64KB
#define SMEM_TOTAL (SM_B + 2 * B_MAT)   // 197632 bytes

// Pre-split prototypes, [k][n] layout (transposed for ldmatrix.trans B frags)
__device__ unsigned short g_bhi[D * NWAY];
__device__ unsigned short g_blo[D * NWAY];
__device__ float g_pn[NWAY];
__device__ float g_ipn[NWAY];

__device__ __forceinline__ uint32_t bf16hi_bits(float v) {
    uint32_t u = __float_as_uint(v);
    return (u + 0x7fffu + ((u >> 16) & 1u)) & 0xffff0000u;
}

// One block per prototype: norms + bf16 hi/lo split into [k][n] globals.
__global__ void proto_prep_kernel(const float* __restrict__ p) {
    int c = blockIdx.x, t = threadIdx.x;   // 64 blocks x 128 threads
    float s = 0.f;
    for (int k = t; k < D; k += 128) {
        float v = p[c * D + k];
        s += v * v;
        uint32_t hb = bf16hi_bits(v);
        float lo = v - __uint_as_float(hb);
        uint32_t lb = bf16hi_bits(lo);
        g_bhi[k * NWAY + c] = (unsigned short)(hb >> 16);
        g_blo[k * NWAY + c] = (unsigned short)(lb >> 16);
    }
    #pragma unroll
    for (int o = 16; o; o >>= 1) s += __shfl_xor_sync(0xffffffffu, s, o);
    __shared__ float ws[4];
    if ((t & 31) == 0) ws[t >> 5] = s;
    __syncthreads();
    if (t == 0) {
        float n2 = ws[0] + ws[1] + ws[2] + ws[3];
        float pn = sqrtf(n2);
        g_pn[c] = pn; g_ipn[c] = 1.0f / pn;
    }
}

// ---------------- PTX helpers (all baseline sm_80+; no arch-suffix features) ----------------
__device__ __forceinline__ uint32_t smem_u32(const void* p) {
    uint32_t a;
    asm("{ .reg .u64 t; cvta.to.shared.u64 t, %1; cvt.u32.u64 %0, t; }" : "=r"(a) : "l"(p));
    return a;
}
__device__ __forceinline__ void ldsm4(uint32_t* r, uint32_t addr) {
    asm volatile("ldmatrix.sync.aligned.m8n8.x4.shared.b16 {%0,%1,%2,%3}, [%4];"
                 : "=r"(r[0]), "=r"(r[1]), "=r"(r[2]), "=r"(r[3]) : "r"(addr));
}
__device__ __forceinline__ void ldsm4t(uint32_t* r, uint32_t addr) {
    asm volatile("ldmatrix.sync.aligned.m8n8.x4.trans.shared.b16 {%0,%1,%2,%3}, [%4];"
                 : "=r"(r[0]), "=r"(r[1]), "=r"(r[2]), "=r"(r[3]) : "r"(addr));
}
__device__ __forceinline__ void mma16816(float* d, const uint32_t* a, const uint32_t* b) {
    asm volatile(
        "mma.sync.aligned.m16n8k16.row.col.f32.bf16.bf16.f32 "
        "{%0,%1,%2,%3}, {%4,%5,%6,%7}, {%8,%9}, {%0,%1,%2,%3};"
        : "+f"(d[0]), "+f"(d[1]), "+f"(d[2]), "+f"(d[3])
        : "r"(a[0]), "r"(a[1]), "r"(a[2]), "r"(a[3]), "r"(b[0]), "r"(b[1]));
}

// exact 2-term bf16 split of a float4
__device__ __forceinline__ void split4(float4 v, uint2& hi, uint2& lo) {
    uint32_t r0 = bf16hi_bits(v.x), r1 = bf16hi_bits(v.y);
    uint32_t r2 = bf16hi_bits(v.z), r3 = bf16hi_bits(v.w);
    hi.x = __byte_perm(r0, r1, 0x7632);
    hi.y = __byte_perm(r2, r3, 0x7632);
    float l0 = v.x - __uint_as_float(r0), l1 = v.y - __uint_as_float(r1);
    float l2 = v.z - __uint_as_float(r2), l3 = v.w - __uint_as_float(r3);
    asm("cvt.rn.bf16x2.f32 %0, %1, %2;" : "=r"(lo.x) : "f"(l1), "f"(l0));
    asm("cvt.rn.bf16x2.f32 %0, %1, %2;" : "=r"(lo.y) : "f"(l3), "f"(l2));
}

__global__ __launch_bounds__(NTH) void cosine_hmma_kernel(
    const float* __restrict__ x, float* __restrict__ out) {

    extern __shared__ char smem[];
    const uint32_t sb = smem_u32(smem);
    const int tid  = threadIdx.x;
    const int wid  = tid >> 5;
    const int lane = tid & 31;
    const int mw   = wid & 3;         // warp m-tile (32 rows)
    const int nw   = wid >> 2;        // warp n-tile (32 cols)
    const long rowBase = (long)blockIdx.x * MT;

    float* xn2s = (float*)(smem + SM_XN2);
    float* spn  = (float*)(smem + SM_SPN);
    float* sipn = (float*)(smem + SM_SIPN);
    if (tid < NWAY) { spn[tid] = g_pn[tid]; sipn[tid] = g_ipn[tid]; }

    // ---- stage B (pre-split, [k][n]) into smem with XOR swizzle: pure copy ----
    {
        const uint4* bh4 = (const uint4*)g_bhi;
        const uint4* bl4 = (const uint4*)g_blo;
        #pragma unroll
        for (int it = 0; it < (D * NWAY / 8) / NTH; it++) {   // 16 chunks/thread
            int c = tid + it * NTH;
            int k = c >> 3, n0 = (c & 7) * 8;
            uint32_t off = (uint32_t)((k >> 3) * 1024 + (k & 7) * 128
                                      + (((k & 7) * 16) ^ (n0 * 2)));
            *(uint4*)(smem + SM_B + off)         = bh4[c];
            *(uint4*)(smem + SM_B + B_MAT + off) = bl4[c];
        }
    }

    // ---- A staging assignment: thread t -> row t>>1, cols (t&1)*32..+31 ----
    const int arow_t = tid >> 1;
    const int acol0  = (tid & 1) * 32;
    float na = 0.f;
    float4 va[8];

    {   // chunk 0 load + stage into buf 0
        const float4* xg = (const float4*)(x + (rowBase + arow_t) * D + acol0);
        #pragma unroll
        for (int i = 0; i < 8; i++) va[i] = xg[i];
        uint32_t rowpart = (uint32_t)((arow_t >> 3) * 1024 + (arow_t & 7) * 128);
        uint32_t sw = (uint32_t)((arow_t & 7) * 16);
        #pragma unroll
        for (int i = 0; i < 8; i++) {
            float4 v = va[i];
            na += v.x * v.x + v.y * v.y + v.z * v.z + v.w * v.w;
            uint2 hi, lo; split4(v, hi, lo);
            uint32_t off = SM_A + rowpart + (sw ^ (uint32_t)((acol0 + 4 * i) * 2));
            *(uint2*)(smem + off)         = hi;
            *(uint2*)(smem + off + A_MAT) = lo;
        }
    }
    __syncthreads();

    // ---- per-lane ldmatrix address constants ----
    const int g = lane >> 3, j = lane & 7;
    // A x4 matrix g: rows (g&1)*8+j of the m16 tile, k-half (g>>1)
    uint32_t arow[2];
    #pragma unroll
    for (int mt = 0; mt < 2; mt++)
        arow[mt] = (uint32_t)((mw * 4 + mt * 2 + (g & 1)) * 1024 + j * 128);
    const uint32_t asw  = (uint32_t)(j * 16);
    const uint32_t akh  = (uint32_t)((g >> 1) * 16);
    // B x4.trans (per pair p): matrix g: k-half (g&1), n-atom 2p + (g>>1)
    uint32_t bfix[2];
    #pragma unroll
    for (int p = 0; p < 2; p++) {
        int nb = nw * 32 + (2 * p + (g >> 1)) * 8;
        bfix[p] = (uint32_t)((g & 1) * 1024 + j * 128 + ((j * 16) ^ (nb * 2)));
    }
    const uint32_t bB = sb + SM_B;

    float acc[2][4][4];
    #pragma unroll
    for (int mt = 0; mt < 2; mt++)
        #pragma unroll
        for (int na4 = 0; na4 < 4; na4++)
            #pragma unroll
            for (int q = 0; q < 4; q++) acc[mt][na4][q] = 0.f;

    // ---- main loop over K chunks ----
    for (int kt = 0; kt < NCH; kt++) {
        if (kt < NCH - 1) {
            const float4* xg = (const float4*)(x + (rowBase + arow_t) * D + (kt + 1) * KT + acol0);
            #pragma unroll
            for (int i = 0; i < 8; i++) va[i] = xg[i];
        }

        const uint32_t abase = sb + SM_A + (uint32_t)((kt & 1) * A_BUF);
        const uint32_t bchunk = (uint32_t)(kt * 8192);   // <<< FIX: chunk kt = k-rows [kt*64, +64) = 8 atoms
        #pragma unroll
        for (int kk = 0; kk < 4; kk++) {
            uint32_t ah[2][4], al[2][4], bh[4][2], bl[4][2];
            uint32_t ac = asw ^ (akh + (uint32_t)(kk * 32));
            ldsm4(ah[0], abase + arow[0] + ac);
            ldsm4(ah[1], abase + arow[1] + ac);
            ldsm4(al[0], abase + A_MAT + arow[0] + ac);
            ldsm4(al[1], abase + A_MAT + arow[1] + ac);
            #pragma unroll
            for (int p = 0; p < 2; p++) {
                uint32_t t4[4];
                ldsm4t(t4, bB + bchunk + bfix[p] + (uint32_t)(kk * 2048));
                bh[2*p][0] = t4[0]; bh[2*p][1] = t4[1];
                bh[2*p+1][0] = t4[2]; bh[2*p+1][1] = t4[3];
                ldsm4t(t4, bB + B_MAT + bchunk + bfix[p] + (uint32_t)(kk * 2048));
                bl[2*p][0] = t4[0]; bl[2*p][1] = t4[1];
                bl[2*p+1][0] = t4[2]; bl[2*p+1][1] = t4[3];
            }
            #pragma unroll
            for (int mt = 0; mt < 2; mt++)
                #pragma unroll
                for (int na4 = 0; na4 < 4; na4++) {
                    mma16816(acc[mt][na4], ah[mt], bh[na4]);
                    mma16816(acc[mt][na4], ah[mt], bl[na4]);
                    mma16816(acc[mt][na4], al[mt], bh[na4]);
                }
        }

        if (kt < NCH - 1) {   // stage chunk kt+1 into the other buffer
            uint32_t rowpart = (uint32_t)((arow_t >> 3) * 1024 + (arow_t & 7) * 128);
            uint32_t sw = (uint32_t)((arow_t & 7) * 16);
            uint32_t base = SM_A + (uint32_t)(((kt + 1) & 1) * A_BUF);
            #pragma unroll
            for (int i = 0; i < 8; i++) {
                float4 v = va[i];
                na += v.x * v.x + v.y * v.y + v.z * v.z + v.w * v.w;
                uint2 hi, lo; split4(v, hi, lo);
                uint32_t off = base + rowpart + (sw ^ (uint32_t)((acol0 + 4 * i) * 2));
                *(uint2*)(smem + off)         = hi;
                *(uint2*)(smem + off + A_MAT) = lo;
            }
        }
        __syncthreads();
    }

    // ---- row norms: pair-reduce (two threads per row, adjacent lanes) ----
    {
        float s = na + __shfl_xor_sync(0xffffffffu, na, 1);
        if ((tid & 1) == 0) xn2s[arow_t] = s;
    }
    __syncthreads();

    // ---- epilogue: scale + store ----
    const int gr = lane >> 2, ci = lane & 3;
    #pragma unroll
    for (int mt = 0; mt < 2; mt++) {
        #pragma unroll
        for (int rr = 0; rr < 2; rr++) {
            int row = mw * 32 + mt * 16 + rr * 8 + gr;
            float n2 = xn2s[row];
            float invxn = rsqrtf(n2);
            float xn = n2 * invxn;
            float* og = out + (rowBase + row) * NWAY;
            #pragma unroll
            for (int na4 = 0; na4 < 4; na4++) {
                int c0 = nw * 32 + na4 * 8 + ci * 2;
                float d0 = acc[mt][na4][rr * 2 + 0];
                float d1 = acc[mt][na4][rr * 2 + 1];
                float den0 = xn * spn[c0], den1 = xn * spn[c0 + 1];
                float s0 = (den0 < 1e-8f) ? 1e8f : invxn * sipn[c0];
                float s1 = (den1 < 1e-8f) ? 1e8f : invxn * sipn[c0 + 1];
                *(float2*)(og + c0) = make_float2(-d0 * s0, -d1 * s1);
            }
        }
    }
}

extern "C" void kernel_launch(void* const* d_in, const int* in_sizes, int n_in,
                              void* d_out, int out_size) {
    const float* x      = (const float*)d_in[0];
    const float* protos = (const float*)d_in[1];
    float* out          = (float*)d_out;
    int B = in_sizes[0] / D;   // 65536

    cudaFuncSetAttribute(cosine_hmma_kernel,
                         cudaFuncAttributeMaxDynamicSharedMemorySize, SMEM_TOTAL);

    proto_prep_kernel<<<NWAY, 128>>>(protos);
    cosine_hmma_kernel<<<B / MT, NTH, SMEM_TOTAL>>>(x, out);
}

// round 5
// speedup vs baseline: 2.0922x; 1.2194x over previous
#include <cuda_runtime.h>
#include <cstdint>

#define D     512
#define NWAY  64
#define MT    128
#define KT    64
#define NCH   (D / KT)     // 8
#define NTH   256

// ---- dynamic smem layout ----
#define A_MAT  16384                    // 128x64 bf16
#define A_BUF  (2 * A_MAT)              // hi + lo
#define B_MAT  8192                     // 64k x 64n bf16 (one chunk)
#define B_BUF  (2 * B_MAT)              // hi + lo
#define SM_XN2  0                       // 128 floats
#define SM_SPN  512                     // 64 floats
#define SM_SIPN 768                     // 64 floats
#define SM_A    1024                    // 2 x A_BUF = 64KB
#define SM_B    (SM_A + 2 * A_BUF)      // 66560: 2 x B_BUF = 32KB
#define SMEM_TOTAL (SM_B + 2 * B_BUF)   // 99328 bytes -> 2 CTAs/SM

// Pre-split prototypes, [k][n] layout (transposed for ldmatrix.trans B frags)
__device__ unsigned short g_bhi[D * NWAY];
__device__ unsigned short g_blo[D * NWAY];
__device__ float g_pn[NWAY];
__device__ float g_ipn[NWAY];

__device__ __forceinline__ uint32_t bf16hi_bits(float v) {
    uint32_t u = __float_as_uint(v);
    return (u + 0x7fffu + ((u >> 16) & 1u)) & 0xffff0000u;
}

__global__ void proto_prep_kernel(const float* __restrict__ p) {
    int c = blockIdx.x, t = threadIdx.x;   // 64 blocks x 128 threads
    float s = 0.f;
    for (int k = t; k < D; k += 128) {
        float v = p[c * D + k];
        s += v * v;
        uint32_t hb = bf16hi_bits(v);
        float lo = v - __uint_as_float(hb);
        uint32_t lb = bf16hi_bits(lo);
        g_bhi[k * NWAY + c] = (unsigned short)(hb >> 16);
        g_blo[k * NWAY + c] = (unsigned short)(lb >> 16);
    }
    #pragma unroll
    for (int o = 16; o; o >>= 1) s += __shfl_xor_sync(0xffffffffu, s, o);
    __shared__ float ws[4];
    if ((t & 31) == 0) ws[t >> 5] = s;
    __syncthreads();
    if (t == 0) {
        float n2 = ws[0] + ws[1] + ws[2] + ws[3];
        float pn = sqrtf(n2);
        g_pn[c] = pn; g_ipn[c] = 1.0f / pn;
    }
}

// ---------------- PTX helpers (baseline sm_80+) ----------------
__device__ __forceinline__ uint32_t smem_u32(const void* p) {
    uint32_t a;
    asm("{ .reg .u64 t; cvta.to.shared.u64 t, %1; cvt.u32.u64 %0, t; }" : "=r"(a) : "l"(p));
    return a;
}
__device__ __forceinline__ void ldsm4(uint32_t* r, uint32_t addr) {
    asm volatile("ldmatrix.sync.aligned.m8n8.x4.shared.b16 {%0,%1,%2,%3}, [%4];"
                 : "=r"(r[0]), "=r"(r[1]), "=r"(r[2]), "=r"(r[3]) : "r"(addr));
}
__device__ __forceinline__ void ldsm4t(uint32_t* r, uint32_t addr) {
    asm volatile("ldmatrix.sync.aligned.m8n8.x4.trans.shared.b16 {%0,%1,%2,%3}, [%4];"
                 : "=r"(r[0]), "=r"(r[1]), "=r"(r[2]), "=r"(r[3]) : "r"(addr));
}
__device__ __forceinline__ void mma16816(float* d, const uint32_t* a, const uint32_t* b) {
    asm volatile(
        "mma.sync.aligned.m16n8k16.row.col.f32.bf16.bf16.f32 "
        "{%0,%1,%2,%3}, {%4,%5,%6,%7}, {%8,%9}, {%0,%1,%2,%3};"
        : "+f"(d[0]), "+f"(d[1]), "+f"(d[2]), "+f"(d[3])
        : "r"(a[0]), "r"(a[1]), "r"(a[2]), "r"(a[3]), "r"(b[0]), "r"(b[1]));
}
__device__ __forceinline__ void cp16(uint32_t saddr, const void* g) {
    asm volatile("cp.async.ca.shared.global [%0], [%1], 16;" :: "r"(saddr), "l"(g));
}
#define CP_COMMIT() asm volatile("cp.async.commit_group;" ::: "memory")
#define CP_WAIT0()  asm volatile("cp.async.wait_group 0;" ::: "memory")

// exact 2-term bf16 split of a float4
__device__ __forceinline__ void split4(float4 v, uint2& hi, uint2& lo) {
    uint32_t r0 = bf16hi_bits(v.x), r1 = bf16hi_bits(v.y);
    uint32_t r2 = bf16hi_bits(v.z), r3 = bf16hi_bits(v.w);
    hi.x = __byte_perm(r0, r1, 0x7632);
    hi.y = __byte_perm(r2, r3, 0x7632);
    float l0 = v.x - __uint_as_float(r0), l1 = v.y - __uint_as_float(r1);
    float l2 = v.z - __uint_as_float(r2), l3 = v.w - __uint_as_float(r3);
    asm("cvt.rn.bf16x2.f32 %0, %1, %2;" : "=r"(lo.x) : "f"(l1), "f"(l0));
    asm("cvt.rn.bf16x2.f32 %0, %1, %2;" : "=r"(lo.y) : "f"(l3), "f"(l2));
}

__global__ __launch_bounds__(NTH, 2) void cosine_hmma_kernel(
    const float* __restrict__ x, float* __restrict__ out) {

    extern __shared__ char smem[];
    const uint32_t sb = smem_u32(smem);
    const int tid  = threadIdx.x;
    const int wid  = tid >> 5;
    const int lane = tid & 31;
    const int mw   = wid & 3;         // warp m-tile (32 rows)
    const int nw   = wid >> 2;        // warp n-tile (32 cols)
    const long rowBase = (long)blockIdx.x * MT;

    float* xn2s = (float*)(smem + SM_XN2);
    float* spn  = (float*)(smem + SM_SPN);
    float* sipn = (float*)(smem + SM_SIPN);
    if (tid < NWAY) { spn[tid] = g_pn[tid]; sipn[tid] = g_ipn[tid]; }

    // ---- B chunk staging via cp.async: thread t copies 2 uint4 per matrix ----
    // smem B tile: 64 k-rows x 128B (64 n x 2B), SW128: off = k*128 + (2n ^ ((k&7)*16))
    auto stage_b = [&](int kt, int buf) {
        const char* bh = (const char*)g_bhi + kt * 8192;
        const char* bl = (const char*)g_blo + kt * 8192;
        uint32_t base = sb + SM_B + (uint32_t)(buf * B_BUF);
        #pragma unroll
        for (int i = 0; i < 2; i++) {
            int c = tid + i * NTH;            // uint4 index (0..511)
            int k = c >> 3, n0 = (c & 7) * 8;
            uint32_t off = (uint32_t)(k * 128 + ((2 * n0) ^ ((k & 7) * 16)));
            cp16(base + off,         bh + c * 16);
            cp16(base + B_MAT + off, bl + c * 16);
        }
    };

    // ---- A staging: thread t -> row t>>1, cols (t&1)*32..+31 ----
    const int arow_t = tid >> 1;
    const int acol0  = (tid & 1) * 32;
    const uint32_t a_rowpart = (uint32_t)((arow_t >> 3) * 1024 + (arow_t & 7) * 128);
    const uint32_t a_sw      = (uint32_t)((arow_t & 7) * 16);
    float na = 0.f;
    float4 va[8];

    {   // prologue: A chunk 0 + B chunk 0 into buf 0
        const float4* xg = (const float4*)(x + (rowBase + arow_t) * D + acol0);
        #pragma unroll
        for (int i = 0; i < 8; i++) va[i] = xg[i];
        stage_b(0, 0);
        CP_COMMIT();
        #pragma unroll
        for (int i = 0; i < 8; i++) {
            float4 v = va[i];
            na += v.x * v.x + v.y * v.y + v.z * v.z + v.w * v.w;
            uint2 hi, lo; split4(v, hi, lo);
            uint32_t off = SM_A + a_rowpart + (a_sw ^ (uint32_t)((acol0 + 4 * i) * 2));
            *(uint2*)(smem + off)         = hi;
            *(uint2*)(smem + off + A_MAT) = lo;
        }
        CP_WAIT0();
    }
    __syncthreads();

    // ---- per-lane ldmatrix address constants ----
    const int g = lane >> 3, j = lane & 7;
    uint32_t arow[2];
    #pragma unroll
    for (int mt = 0; mt < 2; mt++)
        arow[mt] = (uint32_t)((mw * 4 + mt * 2 + (g & 1)) * 1024 + j * 128);
    const uint32_t asw  = (uint32_t)(j * 16);
    const uint32_t akh  = (uint32_t)((g >> 1) * 16);
    uint32_t bfix[2];
    #pragma unroll
    for (int p = 0; p < 2; p++) {
        int nb = nw * 32 + (2 * p + (g >> 1)) * 8;
        bfix[p] = (uint32_t)((g & 1) * 1024 + j * 128 + ((j * 16) ^ (nb * 2)));
    }

    float acc[2][4][4];
    #pragma unroll
    for (int mt = 0; mt < 2; mt++)
        #pragma unroll
        for (int na4 = 0; na4 < 4; na4++)
            #pragma unroll
            for (int q = 0; q < 4; q++) acc[mt][na4][q] = 0.f;

    // ---- main loop over K chunks ----
    for (int kt = 0; kt < NCH; kt++) {
        if (kt < NCH - 1) {
            const float4* xg = (const float4*)(x + (rowBase + arow_t) * D + (kt + 1) * KT + acol0);
            #pragma unroll
            for (int i = 0; i < 8; i++) va[i] = xg[i];
            stage_b(kt + 1, (kt + 1) & 1);
            CP_COMMIT();
        }

        const uint32_t abase = sb + SM_A + (uint32_t)((kt & 1) * A_BUF);
        const uint32_t bbase = sb + SM_B + (uint32_t)((kt & 1) * B_BUF);
        #pragma unroll
        for (int kk = 0; kk < 4; kk++) {
            uint32_t ah[2][4], al[2][4], bh[4][2], bl[4][2];
            uint32_t ac = asw ^ (akh + (uint32_t)(kk * 32));
            ldsm4(ah[0], abase + arow[0] + ac);
            ldsm4(ah[1], abase + arow[1] + ac);
            ldsm4(al[0], abase + A_MAT + arow[0] + ac);
            ldsm4(al[1], abase + A_MAT + arow[1] + ac);
            #pragma unroll
            for (int p = 0; p < 2; p++) {
                uint32_t t4[4];
                ldsm4t(t4, bbase + bfix[p] + (uint32_t)(kk * 2048));
                bh[2*p][0] = t4[0]; bh[2*p][1] = t4[1];
                bh[2*p+1][0] = t4[2]; bh[2*p+1][1] = t4[3];
                ldsm4t(t4, bbase + B_MAT + bfix[p] + (uint32_t)(kk * 2048));
                bl[2*p][0] = t4[0]; bl[2*p][1] = t4[1];
                bl[2*p+1][0] = t4[2]; bl[2*p+1][1] = t4[3];
            }
            #pragma unroll
            for (int mt = 0; mt < 2; mt++)
                #pragma unroll
                for (int na4 = 0; na4 < 4; na4++) {
                    mma16816(acc[mt][na4], ah[mt], bh[na4]);
                    mma16816(acc[mt][na4], ah[mt], bl[na4]);
                    mma16816(acc[mt][na4], al[mt], bh[na4]);
                }
        }

        if (kt < NCH - 1) {   // stage A chunk kt+1 into the other buffer
            uint32_t base = SM_A + (uint32_t)(((kt + 1) & 1) * A_BUF);
            #pragma unroll
            for (int i = 0; i < 8; i++) {
                float4 v = va[i];
                na += v.x * v.x + v.y * v.y + v.z * v.z + v.w * v.w;
                uint2 hi, lo; split4(v, hi, lo);
                uint32_t off = base + a_rowpart + (a_sw ^ (uint32_t)((acol0 + 4 * i) * 2));
                *(uint2*)(smem + off)         = hi;
                *(uint2*)(smem + off + A_MAT) = lo;
            }
            CP_WAIT0();
        }
        __syncthreads();
    }

    // ---- row norms: pair-reduce (two threads per row, adjacent lanes) ----
    {
        float s = na + __shfl_xor_sync(0xffffffffu, na, 1);
        if ((tid & 1) == 0) xn2s[arow_t] = s;
    }
    __syncthreads();

    // ---- epilogue: scale + store ----
    const int gr = lane >> 2, ci = lane & 3;
    #pragma unroll
    for (int mt = 0; mt < 2; mt++) {
        #pragma unroll
        for (int rr = 0; rr < 2; rr++) {
            int row = mw * 32 + mt * 16 + rr * 8 + gr;
            float n2 = xn2s[row];
            float invxn = rsqrtf(n2);
            float xn = n2 * invxn;
            float* og = out + (rowBase + row) * NWAY;
            #pragma unroll
            for (int na4 = 0; na4 < 4; na4++) {
                int c0 = nw * 32 + na4 * 8 + ci * 2;
                float d0 = acc[mt][na4][rr * 2 + 0];
                float d1 = acc[mt][na4][rr * 2 + 1];
                float den0 = xn * spn[c0], den1 = xn * spn[c0 + 1];
                float s0 = (den0 < 1e-8f) ? 1e8f : invxn * sipn[c0];
                float s1 = (den1 < 1e-8f) ? 1e8f : invxn * sipn[c0 + 1];
                *(float2*)(og + c0) = make_float2(-d0 * s0, -d1 * s1);
            }
        }
    }
}

extern "C" void kernel_launch(void* const* d_in, const int* in_sizes, int n_in,
                              void* d_out, int out_size) {
    const float* x      = (const float*)d_in[0];
    const float* protos = (const float*)d_in[1];
    float* out          = (float*)d_out;
    int B = in_sizes[0] / D;   // 65536

    cudaFuncSetAttribute(cosine_hmma_kernel,
                         cudaFuncAttributeMaxDynamicSharedMemorySize, SMEM_TOTAL);

    proto_prep_kernel<<<NWAY, 128>>>(protos);
    cosine_hmma_kernel<<<B / MT, NTH, SMEM_TOTAL>>>(x, out);
}